// round 14
// baseline (speedup 1.0000x reference)
#include <cuda_runtime.h>
#include <cuda_fp16.h>
#include <cstdint>

// Problem constants
#define NROWS   100352        // 2048 windows * 49 tokens
#define DIM     512
#define QKVDIM  1536
#define NWIN    2048
#define NTOK    49
#define NHEAD   16
#define DH      32
#define NMEM    4
#define NCTX    53            // NMEM + NTOK
#define GK      512           // GEMM K (both GEMMs)

#define NCHUNK  4
#define MROWS_C (NROWS / NCHUNK)     // 25088 rows = 196 M-tiles = 512 windows
#define MTILE_C (MROWS_C / 128)      // 196
#define WIN_C   (NWIN / NCHUNK)      // 512

// ---------------------------------------------------------------------------
// Scratch (device globals: no allocation allowed anywhere)
// ---------------------------------------------------------------------------
__device__ __half g_qkv[(size_t)NROWS * QKVDIM];      // 308 MB fp16
__device__ __half g_xh[(size_t)NROWS * DIM];          // LN(x) fp16
__device__ __half g_ah[(size_t)NROWS * DIM];          // attn out fp16
__device__ __half g_wqkv_h[(size_t)QKVDIM * DIM];     // w_qkv^T fp16 [N][K]
__device__ __half g_wout_h[(size_t)DIM * DIM];        // w_out^T fp16 [N][K]
__device__ __half g_biash[16 * 49 * 64];              // per-head bias fp16, mask folded

// ---------------------------------------------------------------------------
// PTX helpers (baseline PTX only -- harness builds for compute_103)
// ---------------------------------------------------------------------------
__device__ __forceinline__ uint32_t smem_u32(const void* p) {
    uint32_t a;
    asm("{ .reg .u64 t; cvta.to.shared.u64 t, %1; cvt.u32.u64 %0, t; }" : "=r"(a) : "l"(p));
    return a;
}
__device__ __forceinline__ void ldmx4(uint32_t* r, uint32_t addr) {
    asm volatile("ldmatrix.sync.aligned.m8n8.x4.shared.b16 {%0,%1,%2,%3}, [%4];"
        : "=r"(r[0]), "=r"(r[1]), "=r"(r[2]), "=r"(r[3]) : "r"(addr));
}
__device__ __forceinline__ void ldmx4t(uint32_t* r, uint32_t addr) {
    asm volatile("ldmatrix.sync.aligned.m8n8.x4.trans.shared.b16 {%0,%1,%2,%3}, [%4];"
        : "=r"(r[0]), "=r"(r[1]), "=r"(r[2]), "=r"(r[3]) : "r"(addr));
}
__device__ __forceinline__ void mma_f16(float* c, const uint32_t* a, const uint32_t* b) {
    asm volatile(
        "mma.sync.aligned.m16n8k16.row.col.f32.f16.f16.f32 "
        "{%0,%1,%2,%3}, {%4,%5,%6,%7}, {%8,%9}, {%0,%1,%2,%3};"
        : "+f"(c[0]), "+f"(c[1]), "+f"(c[2]), "+f"(c[3])
        : "r"(a[0]), "r"(a[1]), "r"(a[2]), "r"(a[3]), "r"(b[0]), "r"(b[1]));
}
__device__ __forceinline__ uint32_t packh2(float a, float b) {
    __half2 t = __floats2half2_rn(a, b);
    return *reinterpret_cast<uint32_t*>(&t);
}
#define CP_ASYNC16(dst, src) \
    asm volatile("cp.async.cg.shared.global [%0], [%1], 16;" :: "r"(dst), "l"(src) : "memory")
#define CP_COMMIT() asm volatile("cp.async.commit_group;" ::: "memory")
#define CP_WAIT1()  asm volatile("cp.async.wait_group 1;" ::: "memory")
#define CP_WAIT0()  asm volatile("cp.async.wait_group 0;" ::: "memory")

// ---------------------------------------------------------------------------
// Kernel 1: fused LayerNorm -> fp16.  One warp per row of 512.
// ---------------------------------------------------------------------------
__global__ void __launch_bounds__(256) ln_prep_kernel(
    const float* __restrict__ x,
    const float* __restrict__ gamma, const float* __restrict__ beta)
{
    int row  = blockIdx.x * 8 + (threadIdx.x >> 5);
    int lane = threadIdx.x & 31;
    const float4* xp = reinterpret_cast<const float4*>(x + (size_t)row * DIM);
    float4 v[4];
    float s = 0.f, sq = 0.f;
#pragma unroll
    for (int i = 0; i < 4; i++) {
        v[i] = xp[lane + i * 32];
        s  += v[i].x + v[i].y + v[i].z + v[i].w;
        sq += v[i].x * v[i].x + v[i].y * v[i].y + v[i].z * v[i].z + v[i].w * v[i].w;
    }
#pragma unroll
    for (int o = 16; o; o >>= 1) {
        s  += __shfl_xor_sync(0xffffffffu, s,  o);
        sq += __shfl_xor_sync(0xffffffffu, sq, o);
    }
    float m   = s * (1.f / DIM);
    float var = sq * (1.f / DIM) - m * m;
    float rs  = rsqrtf(var + 1e-5f);
#pragma unroll
    for (int i = 0; i < 4; i++) {
        int col = (lane + i * 32) * 4;
        float4 gm = *reinterpret_cast<const float4*>(gamma + col);
        float4 bt = *reinterpret_cast<const float4*>(beta + col);
        float y0 = (v[i].x - m) * rs * gm.x + bt.x;
        float y1 = (v[i].y - m) * rs * gm.y + bt.y;
        float y2 = (v[i].z - m) * rs * gm.z + bt.z;
        float y3 = (v[i].w - m) * rs * gm.w + bt.w;
        size_t off = (size_t)row * DIM + col;
        __half2* hp = reinterpret_cast<__half2*>(&g_xh[off]);
        hp[0] = __floats2half2_rn(y0, y1);
        hp[1] = __floats2half2_rn(y2, y3);
    }
}

// ---------------------------------------------------------------------------
// Kernel 2: transpose weights [K,N] -> [N,K] fp16
// ---------------------------------------------------------------------------
__global__ void __launch_bounds__(256) transpose_h_kernel(
    const float* __restrict__ src, __half* __restrict__ dst, int K, int N)
{
    __shared__ float t[32][33];
    int bx = blockIdx.x * 32;   // n base
    int by = blockIdx.y * 32;   // k base
    int tx = threadIdx.x & 31, ty = threadIdx.x >> 5;
#pragma unroll
    for (int u = 0; u < 4; u++)
        t[ty + u * 8][tx] = src[(size_t)(by + ty + u * 8) * N + bx + tx];
    __syncthreads();
#pragma unroll
    for (int u = 0; u < 4; u++)
        dst[(size_t)(bx + ty + u * 8) * K + by + tx] = __float2half_rn(t[tx][ty + u * 8]);
}

// ---------------------------------------------------------------------------
// Kernel 3: per-head bias table, fp16, ctx mask folded in (-6e4 for j>=NCTX)
// ---------------------------------------------------------------------------
__global__ void __launch_bounds__(256) bias_prep_kernel(
    const float* __restrict__ rel_bias, const int* __restrict__ rel_idx)
{
    int idx = blockIdx.x * 256 + threadIdx.x;
    if (idx >= 16 * 49 * 64) return;
    int h = idx / (49 * 64);
    int rem = idx - h * 49 * 64;
    int i = rem >> 6;
    int j = rem & 63;
    float v;
    if (j >= NCTX)      v = -60000.f;
    else if (j < NMEM)  v = 0.f;
    else                v = rel_bias[rel_idx[i * NTOK + (j - NMEM)] * NHEAD + h];
    g_biash[idx] = __float2half_rn(v);
}

// ---------------------------------------------------------------------------
// Tensor-core GEMM, fp16 operands, 3-stage cp.async pipeline, K-slab 64.
// CTA tile 128x128, 8 warps (warp tile 64x32), 2 CTAs/SM.
// m_base: row offset of this chunk (for the 4-chunk pipeline).
// MODE 0: A = g_xh, B = w_qkv^T, C = g_qkv (fp16, N=1536)
// MODE 1: A = g_ah, B = w_out^T, C = out (fp32, N=512)
// ---------------------------------------------------------------------------
#define ROWB     144u                // 64 halves * 2B + 16B pad
#define TILE_B   18432u              // 128 rows * 144 B
#define STAGE_B  36864u              // 2 tiles (A,B)
#define GSMEM    110592              // 3 stages

template <int MODE>
__global__ void __launch_bounds__(256, 2) gemm_mma_kernel(float* __restrict__ Cout, int m_base)
{
    extern __shared__ char smem[];
    const uint32_t sbase = smem_u32(smem);

    const int N = (MODE == 0) ? QKVDIM : DIM;
    const __half* __restrict__ Ah = (MODE == 0) ? g_xh : g_ah;
    const __half* __restrict__ Bh = (MODE == 0) ? g_wqkv_h : g_wout_h;

    const int tid  = threadIdx.x;
    const int lane = tid & 31;
    const int wid  = tid >> 5;
    const int bm   = m_base + blockIdx.y * 128;
    const int bn   = blockIdx.x * 128;
    const int wm   = (wid & 1) * 64;
    const int wn   = (wid >> 1) * 32;

    float c[4][4][4];
#pragma unroll
    for (int i = 0; i < 4; i++)
#pragma unroll
        for (int j = 0; j < 4; j++)
#pragma unroll
            for (int l = 0; l < 4; l++) c[i][j][l] = 0.f;

    auto issue_stage = [&](int buf, int k0) {
#pragma unroll
        for (int u = 0; u < 8; u++) {
            int id   = tid + u * 256;
            int tile = id >> 10;              // 0 = A, 1 = B
            int id10 = id & 1023;
            int r    = id10 >> 3;
            int cch  = id10 & 7;              // 16B chunk (8 halves)
            int grow = ((tile == 0) ? bm : bn) + r;
            const void* src = ((tile == 0) ? Ah : Bh) + (size_t)grow * GK + k0 + cch * 8;
            uint32_t dst = sbase + (uint32_t)buf * STAGE_B + (uint32_t)tile * TILE_B
                         + (uint32_t)r * ROWB + (uint32_t)cch * 16u;
            CP_ASYNC16(dst, src);
        }
        CP_COMMIT();
    };

    issue_stage(0, 0);
    issue_stage(1, 64);

    const int arow = lane & 15;
    const int akof = (lane >> 4) << 3;
    const int brow = (lane & 7) + ((lane >> 4) << 3);
    const int bkof = ((lane >> 3) & 1) << 3;

    for (int it = 0; it < 8; ++it) {
        if (it < 7) CP_WAIT1(); else CP_WAIT0();
        __syncthreads();
        if (it + 2 < 8) issue_stage((it + 2) % 3, (it + 2) * 64);

        const uint32_t st  = sbase + (uint32_t)(it % 3) * STAGE_B;
        const uint32_t pAh = st;
        const uint32_t pBh = st + TILE_B;

#pragma unroll
        for (int h = 0; h < 4; h++) {         // four k16 steps of the 64-slab
            const uint32_t acol = (uint32_t)(h * 16 + akof) * 2u;
            const uint32_t bcol = (uint32_t)(h * 16 + bkof) * 2u;
            uint32_t ah[4][4], bh[4][2];
#pragma unroll
            for (int mt = 0; mt < 4; mt++)
                ldmx4(ah[mt], pAh + (uint32_t)(wm + mt * 16 + arow) * ROWB + acol);
#pragma unroll
            for (int p = 0; p < 2; p++) {
                uint32_t r4[4];
                ldmx4(r4, pBh + (uint32_t)(wn + p * 16 + brow) * ROWB + bcol);
                bh[2 * p][0] = r4[0]; bh[2 * p][1] = r4[1];
                bh[2 * p + 1][0] = r4[2]; bh[2 * p + 1][1] = r4[3];
            }
#pragma unroll
            for (int mt = 0; mt < 4; mt++)
#pragma unroll
                for (int nt = 0; nt < 4; nt++) mma_f16(c[mt][nt], ah[mt], bh[nt]);
        }
    }

    // epilogue
#pragma unroll
    for (int mt = 0; mt < 4; mt++) {
        int row0 = bm + wm + mt * 16 + (lane >> 2);
#pragma unroll
        for (int nt = 0; nt < 4; nt++) {
            int col = bn + wn + nt * 8 + (lane & 3) * 2;
            if (MODE == 0) {
                *reinterpret_cast<__half2*>(&g_qkv[(size_t)row0 * N + col])
                    = __floats2half2_rn(c[mt][nt][0], c[mt][nt][1]);
                *reinterpret_cast<__half2*>(&g_qkv[(size_t)(row0 + 8) * N + col])
                    = __floats2half2_rn(c[mt][nt][2], c[mt][nt][3]);
            } else {
                *reinterpret_cast<float2*>(Cout + (size_t)row0 * N + col)
                    = make_float2(c[mt][nt][0], c[mt][nt][1]);
                *reinterpret_cast<float2*>(Cout + (size_t)(row0 + 8) * N + col)
                    = make_float2(c[mt][nt][2], c[mt][nt][3]);
            }
        }
    }
}

// ---------------------------------------------------------------------------
// Kernel: tensor-core windowed attention, one block (8 warps) per
// (window, head-pair). Warps 0-3 -> head h0, warps 4-7 -> head h0+1.
// ctx trimmed to 7 n8-tiles (cols 56-63 are fully masked: weight == 0).
// w_base: window offset of this chunk.
// ---------------------------------------------------------------------------
__global__ void __launch_bounds__(256) attn_kernel(const float* __restrict__ mem_kv, int w_base)
{
    const int w = w_base + blockIdx.x;
    const int h0 = blockIdx.y * 2;
    const int tid = threadIdx.x;
    const int lane = tid & 31;
    const int wid = tid >> 5;
    const int hh = wid >> 2;         // which head this warp works on
    const int wid4 = wid & 3;        // m-tile within head
    const int h = h0 + hh;

    __shared__ alignas(16) __half qs[2][64][40];
    __shared__ alignas(16) __half ks[2][64][40];
    __shared__ alignas(16) __half vs[2][64][40];

    // zero-pad all tiles (rows beyond valid range must be 0)
    {
        uint4 z = make_uint4(0, 0, 0, 0);
        uint4* q4 = reinterpret_cast<uint4*>(&qs[0][0][0]);
        uint4* k4 = reinterpret_cast<uint4*>(&ks[0][0][0]);
        uint4* v4 = reinterpret_cast<uint4*>(&vs[0][0][0]);
        for (int i = tid; i < 640; i += 256) { q4[i] = z; k4[i] = z; v4[i] = z; }
    }
    __syncthreads();

    // fill q (rows 0..48), k/v (rows 4..52 from qkv, rows 0..3 from mem_kv)
    const __half* qbase = g_qkv + (size_t)w * NTOK * QKVDIM + h0 * DH;
    for (int idx = tid; idx < NTOK * 8; idx += 256) {
        int i   = idx >> 3;
        int sub = idx & 7;
        int h2  = sub >> 2;          // head within pair
        int ch  = (sub & 3) * 8;     // 16B chunk within the 32-half slice
        const __half* rp = qbase + (size_t)i * QKVDIM + h2 * DH;
        *reinterpret_cast<uint4*>(&qs[h2][i][ch])        = *reinterpret_cast<const uint4*>(rp + ch);
        *reinterpret_cast<uint4*>(&ks[h2][i + NMEM][ch]) = *reinterpret_cast<const uint4*>(rp + DIM + ch);
        *reinterpret_cast<uint4*>(&vs[h2][i + NMEM][ch]) = *reinterpret_cast<const uint4*>(rp + 2 * DIM + ch);
    }
    for (int idx = tid; idx < 512; idx += 256) {
        int which = idx >> 8;            // 0 = k, 1 = v
        int rem   = idx & 255;
        int h2    = rem >> 7;
        int r     = (rem >> 5) & 3;
        int d     = rem & 31;
        float val = mem_kv[which * (NHEAD * NMEM * DH) + ((h0 + h2) * NMEM + r) * DH + d];
        (which ? vs : ks)[h2][r][d] = __float2half_rn(val);
    }
    __syncthreads();

    const uint32_t smq = smem_u32(qs[hh]);
    const uint32_t smk = smem_u32(ks[hh]);
    const uint32_t smv = smem_u32(vs[hh]);

    // ---- QK: warp m-tile = wid4, 7 n8-tiles (cols 0..55), k=32
    float s[7][4];
#pragma unroll
    for (int t = 0; t < 7; t++)
#pragma unroll
        for (int l = 0; l < 4; l++) s[t][l] = 0.f;

    const int arow = lane & 15;
    const int akof = (lane >> 4) << 3;
    const int brow = (lane & 7) + ((lane >> 4) << 3);
    const int bkof = ((lane >> 3) & 1) << 3;

#pragma unroll
    for (int k2 = 0; k2 < 2; k2++) {
        uint32_t a[4];
        ldmx4(a, smq + (uint32_t)(wid4 * 16 + arow) * 80u + (uint32_t)(k2 * 16 + akof) * 2u);
#pragma unroll
        for (int p = 0; p < 4; p++) {
            uint32_t r4[4];
            ldmx4(r4, smk + (uint32_t)(p * 16 + brow) * 80u + (uint32_t)(k2 * 16 + bkof) * 2u);
            mma_f16(s[2 * p], a, r4);
            if (p < 3) mma_f16(s[2 * p + 1], a, r4 + 2);
        }
    }

    // ---- scale + bias (mask folded into bias table)
    const float scale = 0.17677669529663687f;   // 1/sqrt(32)
    const int row0 = wid4 * 16 + (lane >> 2);
    const int row1 = row0 + 8;
    const int c0 = (lane & 3) * 2;
    const __half* gb0 = g_biash + (h * 49 + min(row0, 48)) * 64;
    const __half* gb1 = g_biash + (h * 49 + min(row1, 48)) * 64;
#pragma unroll
    for (int t = 0; t < 7; t++) {
        float2 b0 = __half22float2(*reinterpret_cast<const __half2*>(gb0 + t * 8 + c0));
        float2 b1 = __half22float2(*reinterpret_cast<const __half2*>(gb1 + t * 8 + c0));
        s[t][0] = s[t][0] * scale + b0.x;
        s[t][1] = s[t][1] * scale + b0.y;
        s[t][2] = s[t][2] * scale + b1.x;
        s[t][3] = s[t][3] * scale + b1.y;
    }

    // ---- softmax (rows split across 4-lane groups)
    float m0 = -1e30f, m1 = -1e30f;
#pragma unroll
    for (int t = 0; t < 7; t++) {
        m0 = fmaxf(m0, fmaxf(s[t][0], s[t][1]));
        m1 = fmaxf(m1, fmaxf(s[t][2], s[t][3]));
    }
    m0 = fmaxf(m0, __shfl_xor_sync(0xffffffffu, m0, 1));
    m0 = fmaxf(m0, __shfl_xor_sync(0xffffffffu, m0, 2));
    m1 = fmaxf(m1, __shfl_xor_sync(0xffffffffu, m1, 1));
    m1 = fmaxf(m1, __shfl_xor_sync(0xffffffffu, m1, 2));
    float sum0 = 0.f, sum1 = 0.f;
#pragma unroll
    for (int t = 0; t < 7; t++) {
        s[t][0] = __expf(s[t][0] - m0);
        s[t][1] = __expf(s[t][1] - m0);
        s[t][2] = __expf(s[t][2] - m1);
        s[t][3] = __expf(s[t][3] - m1);
        sum0 += s[t][0] + s[t][1];
        sum1 += s[t][2] + s[t][3];
    }
    sum0 += __shfl_xor_sync(0xffffffffu, sum0, 1);
    sum0 += __shfl_xor_sync(0xffffffffu, sum0, 2);
    sum1 += __shfl_xor_sync(0xffffffffu, sum1, 1);
    sum1 += __shfl_xor_sync(0xffffffffu, sum1, 2);
    float inv0 = 1.f / sum0, inv1 = 1.f / sum1;
#pragma unroll
    for (int t = 0; t < 7; t++) {
        s[t][0] *= inv0; s[t][1] *= inv0;
        s[t][2] *= inv1; s[t][3] *= inv1;
    }

    // ---- PV: P (fp16 A-frags from regs, cols 56-63 == 0) @ V
    float o[4][4];
#pragma unroll
    for (int dt = 0; dt < 4; dt++)
#pragma unroll
        for (int l = 0; l < 4; l++) o[dt][l] = 0.f;

#pragma unroll
    for (int kb = 0; kb < 4; kb++) {
        uint32_t pa[4];
        pa[0] = packh2(s[2 * kb][0], s[2 * kb][1]);
        pa[1] = packh2(s[2 * kb][2], s[2 * kb][3]);
        if (kb < 3) {
            pa[2] = packh2(s[2 * kb + 1][0], s[2 * kb + 1][1]);
            pa[3] = packh2(s[2 * kb + 1][2], s[2 * kb + 1][3]);
        } else {
            pa[2] = 0u;
            pa[3] = 0u;
        }
#pragma unroll
        for (int q = 0; q < 2; q++) {
            uint32_t r4[4];
            ldmx4t(r4, smv + (uint32_t)(kb * 16 + (lane & 15)) * 80u
                       + (uint32_t)(((lane >> 4) << 3) + q * 16) * 2u);
            mma_f16(o[2 * q], pa, r4);
            mma_f16(o[2 * q + 1], pa, r4 + 2);
        }
    }

    // ---- store rows < 49 to g_ah (merged heads, fp16)
    if (row0 < NTOK) {
        __half* op = g_ah + ((size_t)w * NTOK + row0) * DIM + h * DH;
#pragma unroll
        for (int dt = 0; dt < 4; dt++)
            *reinterpret_cast<__half2*>(op + dt * 8 + c0)
                = __floats2half2_rn(o[dt][0], o[dt][1]);
    }
    if (row1 < NTOK) {
        __half* op = g_ah + ((size_t)w * NTOK + row1) * DIM + h * DH;
#pragma unroll
        for (int dt = 0; dt < 4; dt++)
            *reinterpret_cast<__half2*>(op + dt * 8 + c0)
                = __floats2half2_rn(o[dt][2], o[dt][3]);
    }
}

// ---------------------------------------------------------------------------
// Launch: 4-chunk cross-kernel pipeline on 3 streams.
//   main: LN, then G0 chunks; s2: attn chunks; s3: G1 chunks.
//   G0(c) -> attn(c) -> G1(c) chained by events; chunks overlap across streams.
// ---------------------------------------------------------------------------
extern "C" void kernel_launch(void* const* d_in, const int* in_sizes, int n_in,
                              void* d_out, int out_size) {
    const float* x        = (const float*)d_in[0];
    const float* ln_gamma = (const float*)d_in[1];
    const float* ln_beta  = (const float*)d_in[2];
    const float* w_qkv    = (const float*)d_in[3];
    const float* mem_kv   = (const float*)d_in[4];
    const float* w_out    = (const float*)d_in[5];
    const float* rel_bias = (const float*)d_in[6];
    const int*   rel_idx  = (const int*)d_in[7];
    float* out = (float*)d_out;

    static cudaStream_t s1 = nullptr, s2 = nullptr, s3 = nullptr;
    static cudaEvent_t ev0 = nullptr, ev1 = nullptr;
    static cudaEvent_t evG0[NCHUNK], evA[NCHUNK], evG1;
    if (!s1) {
        cudaStreamCreateWithFlags(&s1, cudaStreamNonBlocking);
        cudaStreamCreateWithFlags(&s2, cudaStreamNonBlocking);
        cudaStreamCreateWithFlags(&s3, cudaStreamNonBlocking);
        cudaEventCreateWithFlags(&ev0, cudaEventDisableTiming);
        cudaEventCreateWithFlags(&ev1, cudaEventDisableTiming);
        for (int c = 0; c < NCHUNK; c++) {
            cudaEventCreateWithFlags(&evG0[c], cudaEventDisableTiming);
            cudaEventCreateWithFlags(&evA[c], cudaEventDisableTiming);
        }
        cudaEventCreateWithFlags(&evG1, cudaEventDisableTiming);
        cudaFuncSetAttribute(gemm_mma_kernel<0>, cudaFuncAttributeMaxDynamicSharedMemorySize, GSMEM);
        cudaFuncSetAttribute(gemm_mma_kernel<1>, cudaFuncAttributeMaxDynamicSharedMemorySize, GSMEM);
    }

    __half *wqh, *woh;
    cudaGetSymbolAddress((void**)&wqh, g_wqkv_h);
    cudaGetSymbolAddress((void**)&woh, g_wout_h);

    // fork: transposes + bias on s1, LN on main stream (independent)
    cudaEventRecord(ev0, 0);
    cudaStreamWaitEvent(s1, ev0, 0);
    transpose_h_kernel<<<dim3(QKVDIM / 32, DIM / 32), 256, 0, s1>>>(w_qkv, wqh, DIM, QKVDIM);
    transpose_h_kernel<<<dim3(DIM / 32, DIM / 32), 256, 0, s1>>>(w_out, woh, DIM, DIM);
    bias_prep_kernel<<<(16 * 49 * 64 + 255) / 256, 256, 0, s1>>>(rel_bias, rel_idx);
    cudaEventRecord(ev1, s1);

    ln_prep_kernel<<<NROWS / 8, 256>>>(x, ln_gamma, ln_beta);
    cudaStreamWaitEvent(0, ev1, 0);   // join preps before GEMM chain

    // pipelined chunks
    for (int c = 0; c < NCHUNK; c++) {
        gemm_mma_kernel<0><<<dim3(QKVDIM / 128, MTILE_C), 256, GSMEM>>>(nullptr, c * MROWS_C);
        cudaEventRecord(evG0[c], 0);

        cudaStreamWaitEvent(s2, evG0[c], 0);
        attn_kernel<<<dim3(WIN_C, NHEAD / 2), 256, 0, s2>>>(mem_kv, c * WIN_C);
        cudaEventRecord(evA[c], s2);

        cudaStreamWaitEvent(s3, evA[c], 0);
        gemm_mma_kernel<1><<<dim3(DIM / 128, MTILE_C), 256, GSMEM, s3>>>(out, c * MROWS_C);
    }
    cudaEventRecord(evG1, s3);

    // join all forked streams back to the capture stream
    cudaStreamWaitEvent(0, evA[NCHUNK - 1], 0);
    cudaStreamWaitEvent(0, evG1, 0);
}

// round 17
// speedup vs baseline: 1.0267x; 1.0267x over previous
#include <cuda_runtime.h>
#include <cuda_fp16.h>
#include <cstdint>

// Problem constants
#define NROWS   100352        // 2048 windows * 49 tokens
#define DIM     512
#define QKVDIM  1536
#define NWIN    2048
#define NTOK    49
#define NHEAD   16
#define DH      32
#define NMEM    4
#define NCTX    53            // NMEM + NTOK
#define GK      512           // GEMM K (both GEMMs)

// ---------------------------------------------------------------------------
// Scratch (device globals: no allocation allowed anywhere)
// ---------------------------------------------------------------------------
__device__ __half g_qkv[(size_t)NROWS * QKVDIM];      // 308 MB fp16
__device__ __half g_xh[(size_t)NROWS * DIM];          // LN(x) fp16
__device__ __half g_ah[(size_t)NROWS * DIM];          // attn out fp16
__device__ __half g_wqkv_h[(size_t)QKVDIM * DIM];     // w_qkv^T fp16 [N][K]
__device__ __half g_wout_h[(size_t)DIM * DIM];        // w_out^T fp16 [N][K]
__device__ __half g_biash[16 * 49 * 64];              // per-head bias fp16, mask folded

// ---------------------------------------------------------------------------
// PTX helpers (baseline PTX only -- harness builds for compute_103)
// ---------------------------------------------------------------------------
__device__ __forceinline__ uint32_t smem_u32(const void* p) {
    uint32_t a;
    asm("{ .reg .u64 t; cvta.to.shared.u64 t, %1; cvt.u32.u64 %0, t; }" : "=r"(a) : "l"(p));
    return a;
}
__device__ __forceinline__ void ldmx4(uint32_t* r, uint32_t addr) {
    asm volatile("ldmatrix.sync.aligned.m8n8.x4.shared.b16 {%0,%1,%2,%3}, [%4];"
        : "=r"(r[0]), "=r"(r[1]), "=r"(r[2]), "=r"(r[3]) : "r"(addr));
}
__device__ __forceinline__ void ldmx4t(uint32_t* r, uint32_t addr) {
    asm volatile("ldmatrix.sync.aligned.m8n8.x4.trans.shared.b16 {%0,%1,%2,%3}, [%4];"
        : "=r"(r[0]), "=r"(r[1]), "=r"(r[2]), "=r"(r[3]) : "r"(addr));
}
__device__ __forceinline__ void mma_f16(float* c, const uint32_t* a, const uint32_t* b) {
    asm volatile(
        "mma.sync.aligned.m16n8k16.row.col.f32.f16.f16.f32 "
        "{%0,%1,%2,%3}, {%4,%5,%6,%7}, {%8,%9}, {%0,%1,%2,%3};"
        : "+f"(c[0]), "+f"(c[1]), "+f"(c[2]), "+f"(c[3])
        : "r"(a[0]), "r"(a[1]), "r"(a[2]), "r"(a[3]), "r"(b[0]), "r"(b[1]));
}
__device__ __forceinline__ uint32_t packh2(float a, float b) {
    __half2 t = __floats2half2_rn(a, b);
    return *reinterpret_cast<uint32_t*>(&t);
}
#define CP_ASYNC16(dst, src) \
    asm volatile("cp.async.cg.shared.global [%0], [%1], 16;" :: "r"(dst), "l"(src) : "memory")
#define CP_COMMIT() asm volatile("cp.async.commit_group;" ::: "memory")
#define CP_WAIT1()  asm volatile("cp.async.wait_group 1;" ::: "memory")
#define CP_WAIT0()  asm volatile("cp.async.wait_group 0;" ::: "memory")

// ---------------------------------------------------------------------------
// Kernel 1: fused LayerNorm -> fp16.  One warp per row of 512.
// ---------------------------------------------------------------------------
__global__ void __launch_bounds__(256) ln_prep_kernel(
    const float* __restrict__ x,
    const float* __restrict__ gamma, const float* __restrict__ beta)
{
    int row  = blockIdx.x * 8 + (threadIdx.x >> 5);
    int lane = threadIdx.x & 31;
    const float4* xp = reinterpret_cast<const float4*>(x + (size_t)row * DIM);
    float4 v[4];
    float s = 0.f, sq = 0.f;
#pragma unroll
    for (int i = 0; i < 4; i++) {
        v[i] = xp[lane + i * 32];
        s  += v[i].x + v[i].y + v[i].z + v[i].w;
        sq += v[i].x * v[i].x + v[i].y * v[i].y + v[i].z * v[i].z + v[i].w * v[i].w;
    }
#pragma unroll
    for (int o = 16; o; o >>= 1) {
        s  += __shfl_xor_sync(0xffffffffu, s,  o);
        sq += __shfl_xor_sync(0xffffffffu, sq, o);
    }
    float m   = s * (1.f / DIM);
    float var = sq * (1.f / DIM) - m * m;
    float rs  = rsqrtf(var + 1e-5f);
#pragma unroll
    for (int i = 0; i < 4; i++) {
        int col = (lane + i * 32) * 4;
        float4 gm = *reinterpret_cast<const float4*>(gamma + col);
        float4 bt = *reinterpret_cast<const float4*>(beta + col);
        float y0 = (v[i].x - m) * rs * gm.x + bt.x;
        float y1 = (v[i].y - m) * rs * gm.y + bt.y;
        float y2 = (v[i].z - m) * rs * gm.z + bt.z;
        float y3 = (v[i].w - m) * rs * gm.w + bt.w;
        size_t off = (size_t)row * DIM + col;
        __half2* hp = reinterpret_cast<__half2*>(&g_xh[off]);
        hp[0] = __floats2half2_rn(y0, y1);
        hp[1] = __floats2half2_rn(y2, y3);
    }
}

// ---------------------------------------------------------------------------
// Kernel 2: transpose weights [K,N] -> [N,K] fp16
// ---------------------------------------------------------------------------
__global__ void __launch_bounds__(256) transpose_h_kernel(
    const float* __restrict__ src, __half* __restrict__ dst, int K, int N)
{
    __shared__ float t[32][33];
    int bx = blockIdx.x * 32;   // n base
    int by = blockIdx.y * 32;   // k base
    int tx = threadIdx.x & 31, ty = threadIdx.x >> 5;
#pragma unroll
    for (int u = 0; u < 4; u++)
        t[ty + u * 8][tx] = src[(size_t)(by + ty + u * 8) * N + bx + tx];
    __syncthreads();
#pragma unroll
    for (int u = 0; u < 4; u++)
        dst[(size_t)(bx + ty + u * 8) * K + by + tx] = __float2half_rn(t[tx][ty + u * 8]);
}

// ---------------------------------------------------------------------------
// Kernel 3: per-head bias table, fp16, ctx mask folded in (-6e4 for j>=NCTX)
// ---------------------------------------------------------------------------
__global__ void __launch_bounds__(256) bias_prep_kernel(
    const float* __restrict__ rel_bias, const int* __restrict__ rel_idx)
{
    int idx = blockIdx.x * 256 + threadIdx.x;
    if (idx >= 16 * 49 * 64) return;
    int h = idx / (49 * 64);
    int rem = idx - h * 49 * 64;
    int i = rem >> 6;
    int j = rem & 63;
    float v;
    if (j >= NCTX)      v = -60000.f;
    else if (j < NMEM)  v = 0.f;
    else                v = rel_bias[rel_idx[i * NTOK + (j - NMEM)] * NHEAD + h];
    g_biash[idx] = __float2half_rn(v);
}

// ---------------------------------------------------------------------------
// Tensor-core GEMM, fp16 operands, 3-stage cp.async pipeline, K-slab 64.
// CTA tile 128x128, 8 warps (warp tile 64x32), 2 CTAs/SM.
// (Round-8 known-good config: Pareto point for the legacy-mma path.)
// MODE 0: A = g_xh, B = w_qkv^T, C = g_qkv (fp16, N=1536)
// MODE 1: A = g_ah, B = w_out^T, C = out (fp32, N=512)
// ---------------------------------------------------------------------------
#define ROWB     144u                // 64 halves * 2B + 16B pad
#define TILE_B   18432u              // 128 rows * 144 B
#define STAGE_B  36864u              // 2 tiles (A,B)
#define GSMEM    110592              // 3 stages

template <int MODE>
__global__ void __launch_bounds__(256, 2) gemm_mma_kernel(float* __restrict__ Cout)
{
    extern __shared__ char smem[];
    const uint32_t sbase = smem_u32(smem);

    const int N = (MODE == 0) ? QKVDIM : DIM;
    const __half* __restrict__ Ah = (MODE == 0) ? g_xh : g_ah;
    const __half* __restrict__ Bh = (MODE == 0) ? g_wqkv_h : g_wout_h;

    const int tid  = threadIdx.x;
    const int lane = tid & 31;
    const int wid  = tid >> 5;
    const int bm   = blockIdx.y * 128;
    const int bn   = blockIdx.x * 128;
    const int wm   = (wid & 1) * 64;
    const int wn   = (wid >> 1) * 32;

    float c[4][4][4];
#pragma unroll
    for (int i = 0; i < 4; i++)
#pragma unroll
        for (int j = 0; j < 4; j++)
#pragma unroll
            for (int l = 0; l < 4; l++) c[i][j][l] = 0.f;

    auto issue_stage = [&](int buf, int k0) {
#pragma unroll
        for (int u = 0; u < 8; u++) {
            int id   = tid + u * 256;
            int tile = id >> 10;              // 0 = A, 1 = B
            int id10 = id & 1023;
            int r    = id10 >> 3;
            int cch  = id10 & 7;              // 16B chunk (8 halves)
            int grow = ((tile == 0) ? bm : bn) + r;
            const void* src = ((tile == 0) ? Ah : Bh) + (size_t)grow * GK + k0 + cch * 8;
            uint32_t dst = sbase + (uint32_t)buf * STAGE_B + (uint32_t)tile * TILE_B
                         + (uint32_t)r * ROWB + (uint32_t)cch * 16u;
            CP_ASYNC16(dst, src);
        }
        CP_COMMIT();
    };

    issue_stage(0, 0);
    issue_stage(1, 64);

    const int arow = lane & 15;
    const int akof = (lane >> 4) << 3;
    const int brow = (lane & 7) + ((lane >> 4) << 3);
    const int bkof = ((lane >> 3) & 1) << 3;

    for (int it = 0; it < 8; ++it) {
        if (it < 7) CP_WAIT1(); else CP_WAIT0();
        __syncthreads();
        if (it + 2 < 8) issue_stage((it + 2) % 3, (it + 2) * 64);

        const uint32_t st  = sbase + (uint32_t)(it % 3) * STAGE_B;
        const uint32_t pAh = st;
        const uint32_t pBh = st + TILE_B;

#pragma unroll
        for (int h = 0; h < 4; h++) {         // four k16 steps of the 64-slab
            const uint32_t acol = (uint32_t)(h * 16 + akof) * 2u;
            const uint32_t bcol = (uint32_t)(h * 16 + bkof) * 2u;
            uint32_t ah[4][4], bh[4][2];
#pragma unroll
            for (int mt = 0; mt < 4; mt++)
                ldmx4(ah[mt], pAh + (uint32_t)(wm + mt * 16 + arow) * ROWB + acol);
#pragma unroll
            for (int p = 0; p < 2; p++) {
                uint32_t r4[4];
                ldmx4(r4, pBh + (uint32_t)(wn + p * 16 + brow) * ROWB + bcol);
                bh[2 * p][0] = r4[0]; bh[2 * p][1] = r4[1];
                bh[2 * p + 1][0] = r4[2]; bh[2 * p + 1][1] = r4[3];
            }
#pragma unroll
            for (int mt = 0; mt < 4; mt++)
#pragma unroll
                for (int nt = 0; nt < 4; nt++) mma_f16(c[mt][nt], ah[mt], bh[nt]);
        }
    }

    // epilogue
#pragma unroll
    for (int mt = 0; mt < 4; mt++) {
        int row0 = bm + wm + mt * 16 + (lane >> 2);
#pragma unroll
        for (int nt = 0; nt < 4; nt++) {
            int col = bn + wn + nt * 8 + (lane & 3) * 2;
            if (MODE == 0) {
                *reinterpret_cast<__half2*>(&g_qkv[(size_t)row0 * N + col])
                    = __floats2half2_rn(c[mt][nt][0], c[mt][nt][1]);
                *reinterpret_cast<__half2*>(&g_qkv[(size_t)(row0 + 8) * N + col])
                    = __floats2half2_rn(c[mt][nt][2], c[mt][nt][3]);
            } else {
                *reinterpret_cast<float2*>(Cout + (size_t)row0 * N + col)
                    = make_float2(c[mt][nt][0], c[mt][nt][1]);
                *reinterpret_cast<float2*>(Cout + (size_t)(row0 + 8) * N + col)
                    = make_float2(c[mt][nt][2], c[mt][nt][3]);
            }
        }
    }
}

// ---------------------------------------------------------------------------
// Kernel: tensor-core windowed attention, one block (8 warps) per
// (window, head-pair). Warps 0-3 -> head h0, warps 4-7 -> head h0+1.
// ctx trimmed to 7 n8-tiles (cols 56-63 fully masked: weight == 0).
// Single-barrier staging: only k/v pad rows (53-63, cols 0-31) are zeroed;
// q pad rows hold garbage that only reaches never-stored output rows.
// ---------------------------------------------------------------------------
__global__ void __launch_bounds__(256) attn_kernel(const float* __restrict__ mem_kv)
{
    const int w = blockIdx.x;
    const int h0 = blockIdx.y * 2;
    const int tid = threadIdx.x;
    const int lane = tid & 31;
    const int wid = tid >> 5;
    const int hh = wid >> 2;         // which head this warp works on
    const int wid4 = wid & 3;        // m-tile within head
    const int h = h0 + hh;

    __shared__ alignas(16) __half qs[2][64][40];
    __shared__ alignas(16) __half ks[2][64][40];
    __shared__ alignas(16) __half vs[2][64][40];

    // ---- single staging phase: pad-zero + fills (all disjoint regions)

    // zero k/v pad rows 53..63, cols 0..31 (11 rows x 4 chunks x 2 heads x 2 tensors)
    if (tid < 176) {
        int t   = tid / 88;          // 0 = ks, 1 = vs
        int rem = tid - t * 88;
        int h2  = rem / 44;
        int r2  = rem - h2 * 44;
        int r   = 53 + (r2 >> 2);
        int ch  = (r2 & 3) * 8;
        uint4 z = make_uint4(0, 0, 0, 0);
        if (t == 0) *reinterpret_cast<uint4*>(&ks[h2][r][ch]) = z;
        else        *reinterpret_cast<uint4*>(&vs[h2][r][ch]) = z;
    }

    // fill q (rows 0..48), k/v (rows 4..52 from qkv, rows 0..3 from mem_kv)
    const __half* qbase = g_qkv + (size_t)w * NTOK * QKVDIM + h0 * DH;
    for (int idx = tid; idx < NTOK * 8; idx += 256) {
        int i   = idx >> 3;
        int sub = idx & 7;
        int h2  = sub >> 2;          // head within pair
        int ch  = (sub & 3) * 8;     // 16B chunk within the 32-half slice
        const __half* rp = qbase + (size_t)i * QKVDIM + h2 * DH;
        *reinterpret_cast<uint4*>(&qs[h2][i][ch])        = *reinterpret_cast<const uint4*>(rp + ch);
        *reinterpret_cast<uint4*>(&ks[h2][i + NMEM][ch]) = *reinterpret_cast<const uint4*>(rp + DIM + ch);
        *reinterpret_cast<uint4*>(&vs[h2][i + NMEM][ch]) = *reinterpret_cast<const uint4*>(rp + 2 * DIM + ch);
    }
    for (int idx = tid; idx < 512; idx += 256) {
        int which = idx >> 8;            // 0 = k, 1 = v
        int rem   = idx & 255;
        int h2    = rem >> 7;
        int r     = (rem >> 5) & 3;
        int d     = rem & 31;
        float val = mem_kv[which * (NHEAD * NMEM * DH) + ((h0 + h2) * NMEM + r) * DH + d];
        (which ? vs : ks)[h2][r][d] = __float2half_rn(val);
    }
    __syncthreads();

    const uint32_t smq = smem_u32(qs[hh]);
    const uint32_t smk = smem_u32(ks[hh]);
    const uint32_t smv = smem_u32(vs[hh]);

    // ---- QK: warp m-tile = wid4, 7 n8-tiles (cols 0..55), k=32
    float s[7][4];
#pragma unroll
    for (int t = 0; t < 7; t++)
#pragma unroll
        for (int l = 0; l < 4; l++) s[t][l] = 0.f;

    const int arow = lane & 15;
    const int akof = (lane >> 4) << 3;
    const int brow = (lane & 7) + ((lane >> 4) << 3);
    const int bkof = ((lane >> 3) & 1) << 3;

#pragma unroll
    for (int k2 = 0; k2 < 2; k2++) {
        uint32_t a[4];
        ldmx4(a, smq + (uint32_t)(wid4 * 16 + arow) * 80u + (uint32_t)(k2 * 16 + akof) * 2u);
#pragma unroll
        for (int p = 0; p < 4; p++) {
            uint32_t r4[4];
            ldmx4(r4, smk + (uint32_t)(p * 16 + brow) * 80u + (uint32_t)(k2 * 16 + bkof) * 2u);
            mma_f16(s[2 * p], a, r4);
            if (p < 3) mma_f16(s[2 * p + 1], a, r4 + 2);
        }
    }

    // ---- scale + bias (mask folded into bias table)
    const float scale = 0.17677669529663687f;   // 1/sqrt(32)
    const int row0 = wid4 * 16 + (lane >> 2);
    const int row1 = row0 + 8;
    const int c0 = (lane & 3) * 2;
    const __half* gb0 = g_biash + (h * 49 + min(row0, 48)) * 64;
    const __half* gb1 = g_biash + (h * 49 + min(row1, 48)) * 64;
#pragma unroll
    for (int t = 0; t < 7; t++) {
        float2 b0 = __half22float2(*reinterpret_cast<const __half2*>(gb0 + t * 8 + c0));
        float2 b1 = __half22float2(*reinterpret_cast<const __half2*>(gb1 + t * 8 + c0));
        s[t][0] = s[t][0] * scale + b0.x;
        s[t][1] = s[t][1] * scale + b0.y;
        s[t][2] = s[t][2] * scale + b1.x;
        s[t][3] = s[t][3] * scale + b1.y;
    }

    // ---- softmax (rows split across 4-lane groups)
    float m0 = -1e30f, m1 = -1e30f;
#pragma unroll
    for (int t = 0; t < 7; t++) {
        m0 = fmaxf(m0, fmaxf(s[t][0], s[t][1]));
        m1 = fmaxf(m1, fmaxf(s[t][2], s[t][3]));
    }
    m0 = fmaxf(m0, __shfl_xor_sync(0xffffffffu, m0, 1));
    m0 = fmaxf(m0, __shfl_xor_sync(0xffffffffu, m0, 2));
    m1 = fmaxf(m1, __shfl_xor_sync(0xffffffffu, m1, 1));
    m1 = fmaxf(m1, __shfl_xor_sync(0xffffffffu, m1, 2));
    float sum0 = 0.f, sum1 = 0.f;
#pragma unroll
    for (int t = 0; t < 7; t++) {
        s[t][0] = __expf(s[t][0] - m0);
        s[t][1] = __expf(s[t][1] - m0);
        s[t][2] = __expf(s[t][2] - m1);
        s[t][3] = __expf(s[t][3] - m1);
        sum0 += s[t][0] + s[t][1];
        sum1 += s[t][2] + s[t][3];
    }
    sum0 += __shfl_xor_sync(0xffffffffu, sum0, 1);
    sum0 += __shfl_xor_sync(0xffffffffu, sum0, 2);
    sum1 += __shfl_xor_sync(0xffffffffu, sum1, 1);
    sum1 += __shfl_xor_sync(0xffffffffu, sum1, 2);
    float inv0 = 1.f / sum0, inv1 = 1.f / sum1;
#pragma unroll
    for (int t = 0; t < 7; t++) {
        s[t][0] *= inv0; s[t][1] *= inv0;
        s[t][2] *= inv1; s[t][3] *= inv1;
    }

    // ---- PV: P (fp16 A-frags from regs, cols 56-63 == 0) @ V
    float o[4][4];
#pragma unroll
    for (int dt = 0; dt < 4; dt++)
#pragma unroll
        for (int l = 0; l < 4; l++) o[dt][l] = 0.f;

#pragma unroll
    for (int kb = 0; kb < 4; kb++) {
        uint32_t pa[4];
        pa[0] = packh2(s[2 * kb][0], s[2 * kb][1]);
        pa[1] = packh2(s[2 * kb][2], s[2 * kb][3]);
        if (kb < 3) {
            pa[2] = packh2(s[2 * kb + 1][0], s[2 * kb + 1][1]);
            pa[3] = packh2(s[2 * kb + 1][2], s[2 * kb + 1][3]);
        } else {
            pa[2] = 0u;
            pa[3] = 0u;
        }
#pragma unroll
        for (int q = 0; q < 2; q++) {
            uint32_t r4[4];
            ldmx4t(r4, smv + (uint32_t)(kb * 16 + (lane & 15)) * 80u
                       + (uint32_t)(((lane >> 4) << 3) + q * 16) * 2u);
            mma_f16(o[2 * q], pa, r4);
            mma_f16(o[2 * q + 1], pa, r4 + 2);
        }
    }

    // ---- store rows < 49 to g_ah (merged heads, fp16)
    if (row0 < NTOK) {
        __half* op = g_ah + ((size_t)w * NTOK + row0) * DIM + h * DH;
#pragma unroll
        for (int dt = 0; dt < 4; dt++)
            *reinterpret_cast<__half2*>(op + dt * 8 + c0)
                = __floats2half2_rn(o[dt][0], o[dt][1]);
    }
    if (row1 < NTOK) {
        __half* op = g_ah + ((size_t)w * NTOK + row1) * DIM + h * DH;
#pragma unroll
        for (int dt = 0; dt < 4; dt++)
            *reinterpret_cast<__half2*>(op + dt * 8 + c0)
                = __floats2half2_rn(o[dt][2], o[dt][3]);
    }
}

// ---------------------------------------------------------------------------
// Launch: R13 structure (sequential kernel chain; preps forked onto s1)
// ---------------------------------------------------------------------------
extern "C" void kernel_launch(void* const* d_in, const int* in_sizes, int n_in,
                              void* d_out, int out_size) {
    const float* x        = (const float*)d_in[0];
    const float* ln_gamma = (const float*)d_in[1];
    const float* ln_beta  = (const float*)d_in[2];
    const float* w_qkv    = (const float*)d_in[3];
    const float* mem_kv   = (const float*)d_in[4];
    const float* w_out    = (const float*)d_in[5];
    const float* rel_bias = (const float*)d_in[6];
    const int*   rel_idx  = (const int*)d_in[7];
    float* out = (float*)d_out;

    static cudaStream_t s1 = nullptr;
    static cudaEvent_t ev0 = nullptr, ev1 = nullptr;
    if (!s1) {
        cudaStreamCreateWithFlags(&s1, cudaStreamNonBlocking);
        cudaEventCreateWithFlags(&ev0, cudaEventDisableTiming);
        cudaEventCreateWithFlags(&ev1, cudaEventDisableTiming);
        cudaFuncSetAttribute(gemm_mma_kernel<0>, cudaFuncAttributeMaxDynamicSharedMemorySize, GSMEM);
        cudaFuncSetAttribute(gemm_mma_kernel<1>, cudaFuncAttributeMaxDynamicSharedMemorySize, GSMEM);
    }

    __half *wqh, *woh;
    cudaGetSymbolAddress((void**)&wqh, g_wqkv_h);
    cudaGetSymbolAddress((void**)&woh, g_wout_h);

    // fork: transposes + bias on s1, LN on main stream (independent)
    cudaEventRecord(ev0, 0);
    cudaStreamWaitEvent(s1, ev0, 0);
    transpose_h_kernel<<<dim3(QKVDIM / 32, DIM / 32), 256, 0, s1>>>(w_qkv, wqh, DIM, QKVDIM);
    transpose_h_kernel<<<dim3(DIM / 32, DIM / 32), 256, 0, s1>>>(w_out, woh, DIM, DIM);
    bias_prep_kernel<<<(16 * 49 * 64 + 255) / 256, 256, 0, s1>>>(rel_bias, rel_idx);
    cudaEventRecord(ev1, s1);

    ln_prep_kernel<<<NROWS / 8, 256>>>(x, ln_gamma, ln_beta);
    cudaStreamWaitEvent(0, ev1, 0);   // join preps before GEMM chain

    // QKV GEMM (tensor cores): g_qkv = LN(x) @ w_qkv  (fp16 out)
    gemm_mma_kernel<0><<<dim3(QKVDIM / 128, NROWS / 128), 256, GSMEM>>>(nullptr);

    // tensor-core windowed attention per (window, head-pair) -> g_ah (fp16)
    attn_kernel<<<dim3(NWIN, NHEAD / 2), 256>>>(mem_kv);

    // output projection (tensor cores): out = attn_out @ w_out
    gemm_mma_kernel<1><<<dim3(DIM / 128, NROWS / 128), 256, GSMEM>>>(out);
}